// round 2
// baseline (speedup 1.0000x reference)
#include <cuda_runtime.h>
#include <math.h>

#define N_NODES 50000
#define N_EDGES 800000
#define IN_F    256
#define HID     64
#define CAT_F   256   // 4 * HID

// ---------------- static scratch (no allocations allowed) ----------------
__device__ int   g_cnt_in [N_NODES];
__device__ int   g_cnt_out[N_NODES];
__device__ int   g_cursor [N_NODES];
__device__ int   g_csr_off[N_NODES + 1];
__device__ int   g_esrc   [N_EDGES];
__device__ float g_dout_is[N_NODES];
__device__ float g_din_is [N_NODES];
__device__ float g_xw [N_NODES * HID];     // per-layer GEMM output
__device__ float g_cat[N_NODES * CAT_F];   // JK concat of layer outputs
__device__ float g_y  [N_NODES * HID];     // cat @ W_mlp

// ---------------- setup kernels ----------------
__global__ void k_zero() {
    int i = blockIdx.x * blockDim.x + threadIdx.x;
    if (i < N_NODES) { g_cnt_in[i] = 0; g_cnt_out[i] = 0; g_cursor[i] = 0; }
}

__global__ void k_degree(const int* __restrict__ src, const int* __restrict__ dst) {
    int e = blockIdx.x * blockDim.x + threadIdx.x;
    if (e < N_EDGES) {
        atomicAdd(&g_cnt_out[src[e]], 1);
        atomicAdd(&g_cnt_in [dst[e]], 1);
    }
}

// single block, 1024 threads: exclusive scan of in-degrees -> CSR offsets,
// plus rsqrt of clipped degrees.
__global__ void k_scan() {
    __shared__ int part[1024];
    const int CH = (N_NODES + 1023) / 1024;  // 49
    int t = threadIdx.x;
    int beg = t * CH;
    int end = min(beg + CH, N_NODES);
    int s = 0;
    for (int i = beg; i < end; ++i) s += g_cnt_in[i];
    part[t] = s;
    __syncthreads();
    // Hillis-Steele inclusive scan over 1024 partials
    for (int d = 1; d < 1024; d <<= 1) {
        int v   = part[t];
        int add = (t >= d) ? part[t - d] : 0;
        __syncthreads();
        part[t] = v + add;
        __syncthreads();
    }
    int base = (t == 0) ? 0 : part[t - 1];
    for (int i = beg; i < end; ++i) {
        g_csr_off[i] = base;
        int cin = g_cnt_in[i];
        base += cin;
        g_din_is [i] = rsqrtf((float)max(cin, 1));
        g_dout_is[i] = rsqrtf((float)max(g_cnt_out[i], 1));
    }
    if (t == 1023) g_csr_off[N_NODES] = part[1023];
}

__global__ void k_bucket(const int* __restrict__ src, const int* __restrict__ dst) {
    int e = blockIdx.x * blockDim.x + threadIdx.x;
    if (e < N_EDGES) {
        int d = dst[e];
        int p = atomicAdd(&g_cursor[d], 1);
        g_esrc[g_csr_off[d] + p] = src[e];
    }
}

// ---------------- GEMM: C[N,64] = (A .* rowscale) @ W ----------------
// A: [M, *] row-major, logical K columns starting at column acol, row stride lda.
// W: [K, 64] row-major.  BM=64, BN=64, BK=32, 256 threads.
__global__ __launch_bounds__(256) void k_gemm(
    const float* __restrict__ A, int lda, int acol,
    const float* __restrict__ rowscale,     // null -> no scaling
    const float* __restrict__ W, int K,
    float* __restrict__ C)
{
    __shared__ float As[32][64];   // [k][m] (transposed at load)
    __shared__ float Bs[32][64];   // [k][n]

    const int M  = N_NODES;
    const int m0 = blockIdx.x * 64;
    const int tid = threadIdx.x;
    const int tx = tid & 15;       // 16 cols of threads -> 4 output cols each
    const int ty = tid >> 4;       // 16 rows of threads -> 4 output rows each

    float acc[4][4];
    #pragma unroll
    for (int i = 0; i < 4; ++i)
        #pragma unroll
        for (int j = 0; j < 4; ++j) acc[i][j] = 0.f;

    for (int kk = 0; kk < K; kk += 32) {
        // load A tile 64x32 (2 float4 per thread), transpose into As[k][m]
        #pragma unroll
        for (int q = 0; q < 2; ++q) {
            int f  = tid + 256 * q;        // float4 index 0..511
            int r  = f >> 3;               // row within tile (8 float4 per row)
            int k4 = (f & 7) << 2;         // k within tile
            int row = m0 + r;
            float4 v = make_float4(0.f, 0.f, 0.f, 0.f);
            if (row < M) {
                v = *(const float4*)&A[(size_t)row * lda + acol + kk + k4];
                if (rowscale) {
                    float sc = rowscale[row];
                    v.x *= sc; v.y *= sc; v.z *= sc; v.w *= sc;
                }
            }
            As[k4 + 0][r] = v.x;
            As[k4 + 1][r] = v.y;
            As[k4 + 2][r] = v.z;
            As[k4 + 3][r] = v.w;
        }
        // load B tile 32x64 (2 float4 per thread)
        #pragma unroll
        for (int q = 0; q < 2; ++q) {
            int f  = tid + 256 * q;
            int k  = f >> 4;               // 16 float4 per row
            int n4 = (f & 15) << 2;
            *(float4*)&Bs[k][n4] = *(const float4*)&W[(size_t)(kk + k) * 64 + n4];
        }
        __syncthreads();

        #pragma unroll
        for (int k = 0; k < 32; ++k) {
            float4 a = *(const float4*)&As[k][ty << 2];
            float4 b = *(const float4*)&Bs[k][tx << 2];
            acc[0][0] += a.x * b.x; acc[0][1] += a.x * b.y; acc[0][2] += a.x * b.z; acc[0][3] += a.x * b.w;
            acc[1][0] += a.y * b.x; acc[1][1] += a.y * b.y; acc[1][2] += a.y * b.z; acc[1][3] += a.y * b.w;
            acc[2][0] += a.z * b.x; acc[2][1] += a.z * b.y; acc[2][2] += a.z * b.z; acc[2][3] += a.z * b.w;
            acc[3][0] += a.w * b.x; acc[3][1] += a.w * b.y; acc[3][2] += a.w * b.z; acc[3][3] += a.w * b.w;
        }
        __syncthreads();
    }

    #pragma unroll
    for (int i = 0; i < 4; ++i) {
        int row = m0 + (ty << 2) + i;
        if (row < M) {
            float4 v = make_float4(acc[i][0], acc[i][1], acc[i][2], acc[i][3]);
            *(float4*)&C[(size_t)row * 64 + (tx << 2)] = v;
        }
    }
}

// ---------------- CSR aggregation: one warp per node, 64 features ----------------
// out[node*out_stride + col_off + f] = act( din_is[node] * sum_{e in bucket} xin[esrc[e]*64 + f] + bias[f] )
__global__ __launch_bounds__(256) void k_aggregate(
    const float* __restrict__ xin,          // [N, 64]
    float* __restrict__ out, int out_stride, int col_off,
    const float* __restrict__ din_is,       // null -> no scale
    const float* __restrict__ bias,
    int do_relu)
{
    int gwarp = (blockIdx.x * blockDim.x + threadIdx.x) >> 5;
    int lane  = threadIdx.x & 31;
    if (gwarp >= N_NODES) return;

    int beg = g_csr_off[gwarp];
    int end = g_csr_off[gwarp + 1];

    float2 acc = make_float2(0.f, 0.f);
    int e = beg;
    for (; e + 4 <= end; e += 4) {
        int s0 = g_esrc[e + 0];
        int s1 = g_esrc[e + 1];
        int s2 = g_esrc[e + 2];
        int s3 = g_esrc[e + 3];
        float2 v0 = ((const float2*)(xin + (size_t)s0 * 64))[lane];
        float2 v1 = ((const float2*)(xin + (size_t)s1 * 64))[lane];
        float2 v2 = ((const float2*)(xin + (size_t)s2 * 64))[lane];
        float2 v3 = ((const float2*)(xin + (size_t)s3 * 64))[lane];
        acc.x += v0.x + v1.x + v2.x + v3.x;
        acc.y += v0.y + v1.y + v2.y + v3.y;
    }
    for (; e < end; ++e) {
        int s = g_esrc[e];
        float2 v = ((const float2*)(xin + (size_t)s * 64))[lane];
        acc.x += v.x;
        acc.y += v.y;
    }

    if (din_is) {
        float sc = din_is[gwarp];
        acc.x *= sc; acc.y *= sc;
    }
    float2 b2 = ((const float2*)bias)[lane];
    acc.x += b2.x; acc.y += b2.y;
    if (do_relu) {
        acc.x = fmaxf(acc.x, 0.f);
        acc.y = fmaxf(acc.y, 0.f);
    }
    ((float2*)(out + (size_t)gwarp * out_stride + col_off))[lane] = acc;
}

// ---------------- launch ----------------
extern "C" void kernel_launch(void* const* d_in, const int* in_sizes, int n_in,
                              void* d_out, int out_size)
{
    const float* feat  = (const float*)d_in[0];
    const int*   src   = (const int*)  d_in[1];
    const int*   dst   = (const int*)  d_in[2];
    const float* W[4]  = { (const float*)d_in[3], (const float*)d_in[5],
                           (const float*)d_in[7], (const float*)d_in[9] };
    const float* b[4]  = { (const float*)d_in[4], (const float*)d_in[6],
                           (const float*)d_in[8], (const float*)d_in[10] };
    const float* W_mlp = (const float*)d_in[11];
    const float* b_mlp = (const float*)d_in[12];
    float* out = (float*)d_out;

    float* xw;      cudaGetSymbolAddress((void**)&xw,  g_xw);
    float* cat;     cudaGetSymbolAddress((void**)&cat, g_cat);
    float* y;       cudaGetSymbolAddress((void**)&y,   g_y);
    float* dout_is; cudaGetSymbolAddress((void**)&dout_is, g_dout_is);
    float* din_is;  cudaGetSymbolAddress((void**)&din_is,  g_din_is);

    // --- build normalization + CSR (dst-grouped) ---
    k_zero  <<<(N_NODES + 255) / 256, 256>>>();
    k_degree<<<(N_EDGES + 255) / 256, 256>>>(src, dst);
    k_scan  <<<1, 1024>>>();
    k_bucket<<<(N_EDGES + 255) / 256, 256>>>(src, dst);

    const int gemm_blocks = (N_NODES + 63) / 64;
    const int agg_blocks  = (N_NODES * 32 + 255) / 256;

    // --- 4 GCN layers ---
    for (int i = 0; i < 4; ++i) {
        if (i == 0)
            k_gemm<<<gemm_blocks, 256>>>(feat, IN_F, 0, dout_is, W[0], IN_F, xw);
        else
            k_gemm<<<gemm_blocks, 256>>>(cat, CAT_F, (i - 1) * HID, dout_is, W[i], HID, xw);
        k_aggregate<<<agg_blocks, 256>>>(xw, cat, CAT_F, i * HID, din_is, b[i], 1);
    }

    // --- final: y = cat @ W_mlp, then out = segment_sum(y[src], dst) + b_mlp ---
    // (GEMM commutes with the linear segment-sum: saves 4x edge traffic)
    k_gemm<<<gemm_blocks, 256>>>(cat, CAT_F, 0, (const float*)nullptr, W_mlp, CAT_F, y);
    k_aggregate<<<agg_blocks, 256>>>(y, out, HID, 0, (const float*)nullptr, b_mlp, 0);
}

// round 3
// speedup vs baseline: 1.0754x; 1.0754x over previous
#include <cuda_runtime.h>
#include <math.h>
#include <stdint.h>

#define N_NODES 50000
#define N_EDGES 800000
#define IN_F    256
#define HID     64
#define CAT_F   256   // 4 * HID

// ---------------- static scratch (no allocations allowed) ----------------
__device__ int   g_cnt_in [N_NODES];
__device__ int   g_cnt_out[N_NODES];
__device__ int   g_cursor [N_NODES];
__device__ int   g_csr_off[N_NODES + 1];
__device__ int   g_esrc   [N_EDGES];
__device__ float g_dout_is[N_NODES];
__device__ float g_din_is [N_NODES];
__device__ float g_xw [N_NODES * HID];     // per-layer GEMM output
__device__ float g_cat[N_NODES * CAT_F];   // JK concat of layer outputs
__device__ float g_y  [N_NODES * HID];     // cat @ W_mlp

// ---------------- setup kernels ----------------
__global__ void k_zero() {
    int i = blockIdx.x * blockDim.x + threadIdx.x;
    if (i < N_NODES) { g_cnt_in[i] = 0; g_cnt_out[i] = 0; g_cursor[i] = 0; }
}

__global__ void k_degree(const int* __restrict__ src, const int* __restrict__ dst) {
    int e = blockIdx.x * blockDim.x + threadIdx.x;
    if (e < N_EDGES) {
        atomicAdd(&g_cnt_out[src[e]], 1);
        atomicAdd(&g_cnt_in [dst[e]], 1);
    }
}

// single block, 1024 threads: exclusive scan of in-degrees -> CSR offsets,
// plus rsqrt of clipped degrees.
__global__ void k_scan() {
    __shared__ int part[1024];
    const int CH = (N_NODES + 1023) / 1024;  // 49
    int t = threadIdx.x;
    int beg = t * CH;
    int end = min(beg + CH, N_NODES);
    int s = 0;
    for (int i = beg; i < end; ++i) s += g_cnt_in[i];
    part[t] = s;
    __syncthreads();
    for (int d = 1; d < 1024; d <<= 1) {
        int v   = part[t];
        int add = (t >= d) ? part[t - d] : 0;
        __syncthreads();
        part[t] = v + add;
        __syncthreads();
    }
    int base = (t == 0) ? 0 : part[t - 1];
    for (int i = beg; i < end; ++i) {
        g_csr_off[i] = base;
        int cin = g_cnt_in[i];
        base += cin;
        g_din_is [i] = rsqrtf((float)max(cin, 1));
        g_dout_is[i] = rsqrtf((float)max(g_cnt_out[i], 1));
    }
    if (t == 1023) g_csr_off[N_NODES] = part[1023];
}

__global__ void k_bucket(const int* __restrict__ src, const int* __restrict__ dst) {
    int e = blockIdx.x * blockDim.x + threadIdx.x;
    if (e < N_EDGES) {
        int d = dst[e];
        int p = atomicAdd(&g_cursor[d], 1);
        g_esrc[g_csr_off[d] + p] = src[e];
    }
}

// ---------------- tensor-core GEMM (3xTF32): C[N,64] = (A .* rowscale) @ W ----
// A: [M,*] row-major, logical K cols from column acol, row stride lda.
// W: [K,64] row-major. BM=128, BN=64, BK=16, 256 threads (8 warps = 4M x 2N).
// 3xTF32: a = a_hi + a_lo (both tf32); D += ah*bh + al*bh + ah*bl.

__device__ __forceinline__ uint32_t f2tf32(float f) {
    uint32_t r;
    asm("cvt.rna.tf32.f32 %0, %1;" : "=r"(r) : "f"(f));
    return r;
}

__device__ __forceinline__ void mma_tf32(float* d, const uint32_t* a, const uint32_t* b) {
    asm volatile(
        "mma.sync.aligned.m16n8k8.row.col.f32.tf32.tf32.f32 "
        "{%0,%1,%2,%3}, {%4,%5,%6,%7}, {%8,%9}, {%0,%1,%2,%3};"
        : "+f"(d[0]), "+f"(d[1]), "+f"(d[2]), "+f"(d[3])
        : "r"(a[0]), "r"(a[1]), "r"(a[2]), "r"(a[3]), "r"(b[0]), "r"(b[1]));
}

#define TC_LDS 20   // padded k-stride: (20*g + t) mod 32 hits all banks -> conflict-free frags

__global__ __launch_bounds__(256, 2) void k_gemm_tc(
    const float* __restrict__ A, int lda, int acol,
    const float* __restrict__ rowscale,     // null -> no scaling
    const float* __restrict__ W, int K,
    float* __restrict__ C)
{
    __shared__ uint32_t As_hi[128 * TC_LDS];
    __shared__ uint32_t As_lo[128 * TC_LDS];
    __shared__ uint32_t Bs_hi[ 64 * TC_LDS];
    __shared__ uint32_t Bs_lo[ 64 * TC_LDS];

    const int M    = N_NODES;
    const int tid  = threadIdx.x;
    const int lane = tid & 31;
    const int warp = tid >> 5;
    const int gp   = lane >> 2;   // group id 0..7
    const int tg   = lane & 3;    // thread-in-group 0..3
    const int wm   = warp & 3;    // 4 warps along M
    const int wn   = warp >> 2;   // 2 warps along N
    const int m0   = blockIdx.x * 128;

    float acc[2][4][4];
    #pragma unroll
    for (int mi = 0; mi < 2; ++mi)
        #pragma unroll
        for (int ni = 0; ni < 4; ++ni)
            #pragma unroll
            for (int j = 0; j < 4; ++j) acc[mi][ni][j] = 0.f;

    for (int kk = 0; kk < K; kk += 16) {
        // ---- stage A tile [128 x 16] (convert to hi/lo tf32) ----
        #pragma unroll
        for (int q = 0; q < 2; ++q) {
            int f   = tid + 256 * q;         // float4 index 0..511
            int r   = f >> 2;                // 4 float4 per row
            int k4  = (f & 3) << 2;
            int row = m0 + r;
            float4 v = make_float4(0.f, 0.f, 0.f, 0.f);
            if (row < M) {
                v = *(const float4*)&A[(size_t)row * lda + acol + kk + k4];
                if (rowscale) {
                    float s = rowscale[row];
                    v.x *= s; v.y *= s; v.z *= s; v.w *= s;
                }
            }
            uint32_t h0 = f2tf32(v.x), h1 = f2tf32(v.y), h2 = f2tf32(v.z), h3 = f2tf32(v.w);
            uint32_t l0 = f2tf32(v.x - __uint_as_float(h0));
            uint32_t l1 = f2tf32(v.y - __uint_as_float(h1));
            uint32_t l2 = f2tf32(v.z - __uint_as_float(h2));
            uint32_t l3 = f2tf32(v.w - __uint_as_float(h3));
            *(uint4*)&As_hi[r * TC_LDS + k4] = make_uint4(h0, h1, h2, h3);
            *(uint4*)&As_lo[r * TC_LDS + k4] = make_uint4(l0, l1, l2, l3);
        }
        // ---- stage B tile: W[kk..kk+16) x 64, transposed to Bs[n][k] ----
        {
            int n  = tid & 63;
            int kq = tid >> 6;               // 0..3 -> k block of 4
            uint32_t h[4], l[4];
            #pragma unroll
            for (int j = 0; j < 4; ++j) {
                float v = W[(size_t)(kk + kq * 4 + j) * 64 + n];
                h[j] = f2tf32(v);
                l[j] = f2tf32(v - __uint_as_float(h[j]));
            }
            *(uint4*)&Bs_hi[n * TC_LDS + kq * 4] = make_uint4(h[0], h[1], h[2], h[3]);
            *(uint4*)&Bs_lo[n * TC_LDS + kq * 4] = make_uint4(l[0], l[1], l[2], l[3]);
        }
        __syncthreads();

        // ---- compute: 2 k8 steps per chunk ----
        #pragma unroll
        for (int k8 = 0; k8 < 16; k8 += 8) {
            uint32_t ah[2][4], al[2][4];
            #pragma unroll
            for (int mi = 0; mi < 2; ++mi) {
                int mb = wm * 32 + mi * 16;
                int i0 = (mb + gp)     * TC_LDS + k8 + tg;
                int i1 = (mb + gp + 8) * TC_LDS + k8 + tg;
                ah[mi][0] = As_hi[i0];     ah[mi][1] = As_hi[i1];
                ah[mi][2] = As_hi[i0 + 4]; ah[mi][3] = As_hi[i1 + 4];
                al[mi][0] = As_lo[i0];     al[mi][1] = As_lo[i1];
                al[mi][2] = As_lo[i0 + 4]; al[mi][3] = As_lo[i1 + 4];
            }
            #pragma unroll
            for (int ni = 0; ni < 4; ++ni) {
                int nb = wn * 32 + ni * 8;
                int j0 = (nb + gp) * TC_LDS + k8 + tg;
                uint32_t bh[2], bl[2];
                bh[0] = Bs_hi[j0]; bh[1] = Bs_hi[j0 + 4];
                bl[0] = Bs_lo[j0]; bl[1] = Bs_lo[j0 + 4];
                #pragma unroll
                for (int mi = 0; mi < 2; ++mi) {
                    mma_tf32(acc[mi][ni], ah[mi], bh);
                    mma_tf32(acc[mi][ni], al[mi], bh);
                    mma_tf32(acc[mi][ni], ah[mi], bl);
                }
            }
        }
        __syncthreads();
    }

    // ---- epilogue ----
    #pragma unroll
    for (int mi = 0; mi < 2; ++mi) {
        int rbase = m0 + wm * 32 + mi * 16 + gp;
        #pragma unroll
        for (int ni = 0; ni < 4; ++ni) {
            int col = wn * 32 + ni * 8 + 2 * tg;
            if (rbase < N_NODES)
                *(float2*)&C[(size_t)rbase * 64 + col] =
                    make_float2(acc[mi][ni][0], acc[mi][ni][1]);
            if (rbase + 8 < N_NODES)
                *(float2*)&C[(size_t)(rbase + 8) * 64 + col] =
                    make_float2(acc[mi][ni][2], acc[mi][ni][3]);
        }
    }
}

// ---------------- CSR aggregation: one warp per node, 64 features ----------------
__global__ __launch_bounds__(256) void k_aggregate(
    const float* __restrict__ xin,          // [N, 64]
    float* __restrict__ out, int out_stride, int col_off,
    const float* __restrict__ din_is,       // null -> no scale
    const float* __restrict__ bias,
    int do_relu)
{
    int gwarp = (blockIdx.x * blockDim.x + threadIdx.x) >> 5;
    int lane  = threadIdx.x & 31;
    if (gwarp >= N_NODES) return;

    int beg = g_csr_off[gwarp];
    int end = g_csr_off[gwarp + 1];

    float2 acc = make_float2(0.f, 0.f);
    int e = beg;
    for (; e + 4 <= end; e += 4) {
        int s0 = g_esrc[e + 0];
        int s1 = g_esrc[e + 1];
        int s2 = g_esrc[e + 2];
        int s3 = g_esrc[e + 3];
        float2 v0 = ((const float2*)(xin + (size_t)s0 * 64))[lane];
        float2 v1 = ((const float2*)(xin + (size_t)s1 * 64))[lane];
        float2 v2 = ((const float2*)(xin + (size_t)s2 * 64))[lane];
        float2 v3 = ((const float2*)(xin + (size_t)s3 * 64))[lane];
        acc.x += v0.x + v1.x + v2.x + v3.x;
        acc.y += v0.y + v1.y + v2.y + v3.y;
    }
    for (; e < end; ++e) {
        int s = g_esrc[e];
        float2 v = ((const float2*)(xin + (size_t)s * 64))[lane];
        acc.x += v.x;
        acc.y += v.y;
    }

    if (din_is) {
        float sc = din_is[gwarp];
        acc.x *= sc; acc.y *= sc;
    }
    float2 b2 = ((const float2*)bias)[lane];
    acc.x += b2.x; acc.y += b2.y;
    if (do_relu) {
        acc.x = fmaxf(acc.x, 0.f);
        acc.y = fmaxf(acc.y, 0.f);
    }
    ((float2*)(out + (size_t)gwarp * out_stride + col_off))[lane] = acc;
}

// ---------------- launch ----------------
extern "C" void kernel_launch(void* const* d_in, const int* in_sizes, int n_in,
                              void* d_out, int out_size)
{
    const float* feat  = (const float*)d_in[0];
    const int*   src   = (const int*)  d_in[1];
    const int*   dst   = (const int*)  d_in[2];
    const float* W[4]  = { (const float*)d_in[3], (const float*)d_in[5],
                           (const float*)d_in[7], (const float*)d_in[9] };
    const float* b[4]  = { (const float*)d_in[4], (const float*)d_in[6],
                           (const float*)d_in[8], (const float*)d_in[10] };
    const float* W_mlp = (const float*)d_in[11];
    const float* b_mlp = (const float*)d_in[12];
    float* out = (float*)d_out;

    float* xw;      cudaGetSymbolAddress((void**)&xw,  g_xw);
    float* cat;     cudaGetSymbolAddress((void**)&cat, g_cat);
    float* y;       cudaGetSymbolAddress((void**)&y,   g_y);
    float* dout_is; cudaGetSymbolAddress((void**)&dout_is, g_dout_is);
    float* din_is;  cudaGetSymbolAddress((void**)&din_is,  g_din_is);

    // --- build normalization + CSR (dst-grouped) ---
    k_zero  <<<(N_NODES + 255) / 256, 256>>>();
    k_degree<<<(N_EDGES + 255) / 256, 256>>>(src, dst);
    k_scan  <<<1, 1024>>>();
    k_bucket<<<(N_EDGES + 255) / 256, 256>>>(src, dst);

    const int gemm_blocks = (N_NODES + 127) / 128;
    const int agg_blocks  = (N_NODES * 32 + 255) / 256;

    // --- 4 GCN layers ---
    for (int i = 0; i < 4; ++i) {
        if (i == 0)
            k_gemm_tc<<<gemm_blocks, 256>>>(feat, IN_F, 0, dout_is, W[0], IN_F, xw);
        else
            k_gemm_tc<<<gemm_blocks, 256>>>(cat, CAT_F, (i - 1) * HID, dout_is, W[i], HID, xw);
        k_aggregate<<<agg_blocks, 256>>>(xw, cat, CAT_F, i * HID, din_is, b[i], 1);
    }

    // --- final: y = cat @ W_mlp, then out = segment_sum(y[src], dst) + b_mlp ---
    k_gemm_tc<<<gemm_blocks, 256>>>(cat, CAT_F, 0, (const float*)nullptr, W_mlp, CAT_F, y);
    k_aggregate<<<agg_blocks, 256>>>(y, out, HID, 0, (const float*)nullptr, b_mlp, 0);
}

// round 4
// speedup vs baseline: 1.0790x; 1.0034x over previous
#include <cuda_runtime.h>
#include <math.h>
#include <stdint.h>

#define N_NODES 50000
#define N_EDGES 800000
#define IN_F    256
#define HID     64
#define CAT_F   256   // 4 * HID

// ---------------- static scratch (no allocations allowed) ----------------
__device__ int   g_cnt_in [N_NODES];
__device__ int   g_cnt_out[N_NODES];
__device__ int   g_cursor [N_NODES];
__device__ int   g_csr_off[N_NODES + 1];
__device__ int   g_esrc   [N_EDGES];
__device__ float g_dout_is[N_NODES];
__device__ float g_din_is [N_NODES];
__device__ float g_xw [N_NODES * HID];     // per-layer GEMM output
__device__ float g_cat[N_NODES * CAT_F];   // JK concat of layer outputs
__device__ float g_y  [N_NODES * HID];     // cat @ W_mlp

// ---------------- small setup kernels ----------------
__global__ void k_zero() {
    int i = blockIdx.x * blockDim.x + threadIdx.x;
    if (i < N_NODES) { g_cnt_in[i] = 0; g_cnt_out[i] = 0; g_cursor[i] = 0; }
}

// single block, 1024 threads: exclusive scan of in-degrees -> CSR offsets,
// plus rsqrt of clipped degrees.
__global__ void k_scan() {
    __shared__ int part[1024];
    const int CH = (N_NODES + 1023) / 1024;  // 49
    int t = threadIdx.x;
    int beg = t * CH;
    int end = min(beg + CH, N_NODES);
    int s = 0;
    for (int i = beg; i < end; ++i) s += g_cnt_in[i];
    part[t] = s;
    __syncthreads();
    for (int d = 1; d < 1024; d <<= 1) {
        int v   = part[t];
        int add = (t >= d) ? part[t - d] : 0;
        __syncthreads();
        part[t] = v + add;
        __syncthreads();
    }
    int base = (t == 0) ? 0 : part[t - 1];
    for (int i = beg; i < end; ++i) {
        g_csr_off[i] = base;
        int cin = g_cnt_in[i];
        base += cin;
        g_din_is [i] = rsqrtf((float)max(cin, 1));
        g_dout_is[i] = rsqrtf((float)max(g_cnt_out[i], 1));
    }
    if (t == 1023) g_csr_off[N_NODES] = part[1023];
}

__global__ void k_bucket(const int* __restrict__ src, const int* __restrict__ dst) {
    int e = blockIdx.x * blockDim.x + threadIdx.x;
    if (e < N_EDGES) {
        int d = dst[e];
        int p = atomicAdd(&g_cursor[d], 1);
        g_esrc[g_csr_off[d] + p] = src[e];
    }
}

// ---------------- tensor-core GEMM (3xTF32): C[N,64] = A @ W ---------------
// A: [M,*] row-major, logical K cols from column acol, row stride lda.
// W: [K,64] row-major. BM=128, BN=64, BK=16, 256 threads (8 warps = 4M x 2N).
// 3xTF32: a = a_hi + a_lo (both tf32); D += ah*bh + al*bh + ah*bl.

__device__ __forceinline__ uint32_t f2tf32(float f) {
    uint32_t r;
    asm("cvt.rna.tf32.f32 %0, %1;" : "=r"(r) : "f"(f));
    return r;
}

__device__ __forceinline__ void mma_tf32(float* d, const uint32_t* a, const uint32_t* b) {
    asm volatile(
        "mma.sync.aligned.m16n8k8.row.col.f32.tf32.tf32.f32 "
        "{%0,%1,%2,%3}, {%4,%5,%6,%7}, {%8,%9}, {%0,%1,%2,%3};"
        : "+f"(d[0]), "+f"(d[1]), "+f"(d[2]), "+f"(d[3])
        : "r"(a[0]), "r"(a[1]), "r"(a[2]), "r"(a[3]), "r"(b[0]), "r"(b[1]));
}

#define TC_LDS 20   // padded k-stride: (20*g + t) mod 32 hits all banks -> conflict-free frags

__device__ __forceinline__ void gemm_tc_block(
    int bx,
    const float* __restrict__ A, int lda, int acol,
    const float* __restrict__ W, int K,
    float* __restrict__ C)
{
    __shared__ uint32_t As_hi[128 * TC_LDS];
    __shared__ uint32_t As_lo[128 * TC_LDS];
    __shared__ uint32_t Bs_hi[ 64 * TC_LDS];
    __shared__ uint32_t Bs_lo[ 64 * TC_LDS];

    const int M    = N_NODES;
    const int tid  = threadIdx.x;
    const int lane = tid & 31;
    const int warp = tid >> 5;
    const int gp   = lane >> 2;   // group id 0..7
    const int tg   = lane & 3;    // thread-in-group 0..3
    const int wm   = warp & 3;    // 4 warps along M
    const int wn   = warp >> 2;   // 2 warps along N
    const int m0   = bx * 128;

    float acc[2][4][4];
    #pragma unroll
    for (int mi = 0; mi < 2; ++mi)
        #pragma unroll
        for (int ni = 0; ni < 4; ++ni)
            #pragma unroll
            for (int j = 0; j < 4; ++j) acc[mi][ni][j] = 0.f;

    for (int kk = 0; kk < K; kk += 16) {
        // ---- stage A tile [128 x 16] (convert to hi/lo tf32) ----
        #pragma unroll
        for (int q = 0; q < 2; ++q) {
            int f   = tid + 256 * q;         // float4 index 0..511
            int r   = f >> 2;                // 4 float4 per row
            int k4  = (f & 3) << 2;
            int row = m0 + r;
            float4 v = make_float4(0.f, 0.f, 0.f, 0.f);
            if (row < M)
                v = *(const float4*)&A[(size_t)row * lda + acol + kk + k4];
            uint32_t h0 = f2tf32(v.x), h1 = f2tf32(v.y), h2 = f2tf32(v.z), h3 = f2tf32(v.w);
            uint32_t l0 = f2tf32(v.x - __uint_as_float(h0));
            uint32_t l1 = f2tf32(v.y - __uint_as_float(h1));
            uint32_t l2 = f2tf32(v.z - __uint_as_float(h2));
            uint32_t l3 = f2tf32(v.w - __uint_as_float(h3));
            *(uint4*)&As_hi[r * TC_LDS + k4] = make_uint4(h0, h1, h2, h3);
            *(uint4*)&As_lo[r * TC_LDS + k4] = make_uint4(l0, l1, l2, l3);
        }
        // ---- stage B tile: W[kk..kk+16) x 64, transposed to Bs[n][k] ----
        {
            int n  = tid & 63;
            int kq = tid >> 6;               // 0..3 -> k block of 4
            uint32_t h[4], l[4];
            #pragma unroll
            for (int j = 0; j < 4; ++j) {
                float v = W[(size_t)(kk + kq * 4 + j) * 64 + n];
                h[j] = f2tf32(v);
                l[j] = f2tf32(v - __uint_as_float(h[j]));
            }
            *(uint4*)&Bs_hi[n * TC_LDS + kq * 4] = make_uint4(h[0], h[1], h[2], h[3]);
            *(uint4*)&Bs_lo[n * TC_LDS + kq * 4] = make_uint4(l[0], l[1], l[2], l[3]);
        }
        __syncthreads();

        // ---- compute: 2 k8 steps per chunk ----
        #pragma unroll
        for (int k8 = 0; k8 < 16; k8 += 8) {
            uint32_t ah[2][4], al[2][4];
            #pragma unroll
            for (int mi = 0; mi < 2; ++mi) {
                int mb = wm * 32 + mi * 16;
                int i0 = (mb + gp)     * TC_LDS + k8 + tg;
                int i1 = (mb + gp + 8) * TC_LDS + k8 + tg;
                ah[mi][0] = As_hi[i0];     ah[mi][1] = As_hi[i1];
                ah[mi][2] = As_hi[i0 + 4]; ah[mi][3] = As_hi[i1 + 4];
                al[mi][0] = As_lo[i0];     al[mi][1] = As_lo[i1];
                al[mi][2] = As_lo[i0 + 4]; al[mi][3] = As_lo[i1 + 4];
            }
            #pragma unroll
            for (int ni = 0; ni < 4; ++ni) {
                int nb = wn * 32 + ni * 8;
                int j0 = (nb + gp) * TC_LDS + k8 + tg;
                uint32_t bh[2], bl[2];
                bh[0] = Bs_hi[j0]; bh[1] = Bs_hi[j0 + 4];
                bl[0] = Bs_lo[j0]; bl[1] = Bs_lo[j0 + 4];
                #pragma unroll
                for (int mi = 0; mi < 2; ++mi) {
                    mma_tf32(acc[mi][ni], ah[mi], bh);
                    mma_tf32(acc[mi][ni], al[mi], bh);
                    mma_tf32(acc[mi][ni], ah[mi], bl);
                }
            }
        }
        __syncthreads();
    }

    // ---- epilogue ----
    #pragma unroll
    for (int mi = 0; mi < 2; ++mi) {
        int rbase = m0 + wm * 32 + mi * 16 + gp;
        #pragma unroll
        for (int ni = 0; ni < 4; ++ni) {
            int col = wn * 32 + ni * 8 + 2 * tg;
            if (rbase < N_NODES)
                *(float2*)&C[(size_t)rbase * 64 + col] =
                    make_float2(acc[mi][ni][0], acc[mi][ni][1]);
            if (rbase + 8 < N_NODES)
                *(float2*)&C[(size_t)(rbase + 8) * 64 + col] =
                    make_float2(acc[mi][ni][2], acc[mi][ni][3]);
        }
    }
}

__global__ __launch_bounds__(256, 2) void k_gemm_tc(
    const float* __restrict__ A, int lda, int acol,
    const float* __restrict__ W, int K,
    float* __restrict__ C)
{
    gemm_tc_block(blockIdx.x, A, lda, acol, W, K, C);
}

// Fused: GEMM0 (feat @ W0, unscaled) on blocks [0, gemm_blocks),
// degree counting on blocks [gemm_blocks, gemm_blocks + 3125).
// Independent work -> runs concurrently in one launch.
__global__ __launch_bounds__(256, 2) void k_phase1(
    const float* __restrict__ feat, const float* __restrict__ W0,
    const int* __restrict__ src, const int* __restrict__ dst,
    int gemm_blocks, float* __restrict__ xw)
{
    if (blockIdx.x < (unsigned)gemm_blocks) {
        gemm_tc_block(blockIdx.x, feat, IN_F, 0, W0, IN_F, xw);
    } else {
        int e = (blockIdx.x - gemm_blocks) * 256 + threadIdx.x;
        if (e < N_EDGES) {
            atomicAdd(&g_cnt_out[src[e]], 1);
            atomicAdd(&g_cnt_in [dst[e]], 1);
        }
    }
}

// ---------------- CSR aggregation: one warp per node, 64 features ----------
// out[n, col_off+f] = act( din_is[n]? * sum_e dout_is[src_e]? * xin[src_e, f] + bias[f] )
template<bool EDGE_SCALE, bool DST_SCALE, bool RELU>
__global__ __launch_bounds__(256) void k_aggregate(
    const float* __restrict__ xin,          // [N, 64]
    float* __restrict__ out, int out_stride, int col_off,
    const float* __restrict__ bias)
{
    int gwarp = (blockIdx.x * blockDim.x + threadIdx.x) >> 5;
    int lane  = threadIdx.x & 31;
    if (gwarp >= N_NODES) return;

    int beg = g_csr_off[gwarp];
    int end = g_csr_off[gwarp + 1];

    float2 acc = make_float2(0.f, 0.f);
    int e = beg;
    for (; e + 8 <= end; e += 8) {
        int s[8];
        #pragma unroll
        for (int j = 0; j < 8; ++j) s[j] = g_esrc[e + j];
        float w[8];
        #pragma unroll
        for (int j = 0; j < 8; ++j) w[j] = EDGE_SCALE ? g_dout_is[s[j]] : 1.f;
        float2 v[8];
        #pragma unroll
        for (int j = 0; j < 8; ++j)
            v[j] = ((const float2*)(xin + (size_t)s[j] * 64))[lane];
        #pragma unroll
        for (int j = 0; j < 8; ++j) {
            if (EDGE_SCALE) { acc.x += w[j] * v[j].x; acc.y += w[j] * v[j].y; }
            else            { acc.x += v[j].x;        acc.y += v[j].y; }
        }
    }
    for (; e < end; ++e) {
        int s = g_esrc[e];
        float2 v = ((const float2*)(xin + (size_t)s * 64))[lane];
        if (EDGE_SCALE) {
            float w = g_dout_is[s];
            acc.x += w * v.x; acc.y += w * v.y;
        } else {
            acc.x += v.x; acc.y += v.y;
        }
    }

    if (DST_SCALE) {
        float sc = g_din_is[gwarp];
        acc.x *= sc; acc.y *= sc;
    }
    float2 b2 = ((const float2*)bias)[lane];
    acc.x += b2.x; acc.y += b2.y;
    if (RELU) {
        acc.x = fmaxf(acc.x, 0.f);
        acc.y = fmaxf(acc.y, 0.f);
    }
    ((float2*)(out + (size_t)gwarp * out_stride + col_off))[lane] = acc;
}

// ---------------- launch ----------------
extern "C" void kernel_launch(void* const* d_in, const int* in_sizes, int n_in,
                              void* d_out, int out_size)
{
    const float* feat  = (const float*)d_in[0];
    const int*   src   = (const int*)  d_in[1];
    const int*   dst   = (const int*)  d_in[2];
    const float* W[4]  = { (const float*)d_in[3], (const float*)d_in[5],
                           (const float*)d_in[7], (const float*)d_in[9] };
    const float* b[4]  = { (const float*)d_in[4], (const float*)d_in[6],
                           (const float*)d_in[8], (const float*)d_in[10] };
    const float* W_mlp = (const float*)d_in[11];
    const float* b_mlp = (const float*)d_in[12];
    float* out = (float*)d_out;

    float* xw;  cudaGetSymbolAddress((void**)&xw,  g_xw);
    float* cat; cudaGetSymbolAddress((void**)&cat, g_cat);
    float* y;   cudaGetSymbolAddress((void**)&y,   g_y);

    const int gemm_blocks = (N_NODES + 127) / 128;           // 391
    const int deg_blocks  = (N_EDGES + 255) / 256;           // 3125
    const int agg_blocks  = (N_NODES * 32 + 255) / 256;

    // --- CSR build, with GEMM0 (dout-scale commuted to aggregate) fused in ---
    k_zero  <<<(N_NODES + 255) / 256, 256>>>();
    k_phase1<<<gemm_blocks + deg_blocks, 256>>>(feat, W[0], src, dst, gemm_blocks, xw);
    k_scan  <<<1, 1024>>>();
    k_bucket<<<deg_blocks, 256>>>(src, dst);

    // --- 4 GCN layers (edge-side dout scaling inside aggregate) ---
    k_aggregate<true, true, true><<<agg_blocks, 256>>>(xw, cat, CAT_F, 0, b[0]);
    for (int i = 1; i < 4; ++i) {
        k_gemm_tc<<<gemm_blocks, 256>>>(cat, CAT_F, (i - 1) * HID, W[i], HID, xw);
        k_aggregate<true, true, true><<<agg_blocks, 256>>>(xw, cat, CAT_F, i * HID, b[i]);
    }

    // --- final: y = cat @ W_mlp, then out = segment_sum(y[src], dst) + b_mlp ---
    k_gemm_tc<<<gemm_blocks, 256>>>(cat, CAT_F, 0, W_mlp, CAT_F, y);
    k_aggregate<false, false, false><<<agg_blocks, 256>>>(y, out, HID, 0, b_mlp);
}